// round 12
// baseline (speedup 1.0000x reference)
#include <cuda_runtime.h>

// ---------------- problem constants ----------------
#define TBS   128          // T*B = 4*32
#define SEQ   81           // 9*9
#define CH    128          // width C
#define MROWS (TBS*SEQ)    // 10368 rows
#define NQKV  384          // 3*C
#define EPSLN 1e-5f

typedef unsigned long long ull;

// ---------------- scratch (static device globals; no allocation) ------------
__device__ float  g_h  [MROWS*CH];    // residual stream
__device__ float4 g_part[MROWS];      // per-row (s0, ss0, s1, ss1) stats partials
__device__ float  g_qkv[MROWS*NQKV];  // qkv projection
__device__ float  g_att[MROWS*CH];    // attention output

// ---------------- packed f32x2 helpers --------------------------------------
__device__ __forceinline__ ull pk2(float x, float y) {
    ull r;
    asm("mov.b64 %0, {%1, %2};"
        : "=l"(r) : "r"(__float_as_uint(x)), "r"(__float_as_uint(y)));
    return r;
}
__device__ __forceinline__ ull fma2(ull a, ull b, ull c) {
    ull d;
    asm("fma.rn.f32x2 %0, %1, %2, %3;" : "=l"(d) : "l"(a), "l"(b), "l"(c));
    return d;
}
__device__ __forceinline__ void upk2(ull v, float& x, float& y) {
    unsigned int lo, hi;
    asm("mov.b64 {%0, %1}, %2;" : "=r"(lo), "=r"(hi) : "l"(v));
    x = __uint_as_float(lo);
    y = __uint_as_float(hi);
}
__device__ __forceinline__ float ex2(float x) {
    float r;
    asm("ex2.approx.f32 %0, %1;" : "=f"(r) : "f"(x));
    return r;
}

// ---------------- input projection + stats partials --------------------------
__global__ void __launch_bounds__(256) inproj_kernel(const float* __restrict__ x,
                                                     const float* __restrict__ in_w,
                                                     const float* __restrict__ in_b) {
    int row  = blockIdx.x * 8 + (threadIdx.x >> 5);
    int lane = threadIdx.x & 31;
    float x0 = __ldg(&x[row * 2]);
    float x1 = __ldg(&x[row * 2 + 1]);
    float s = 0.f, ss = 0.f;
    float* hr = g_h + (size_t)row * CH;
#pragma unroll
    for (int j = 0; j < 4; j++) {
        int c = lane + 32 * j;
        float h = fmaf(x0, in_w[c], fmaf(x1, in_w[CH + c], in_b[c]));
        hr[c] = h;
        s += h;
        ss = fmaf(h, h, ss);
    }
#pragma unroll
    for (int o = 16; o; o >>= 1) {
        s  += __shfl_xor_sync(0xffffffffu, s, o);
        ss += __shfl_xor_sync(0xffffffffu, ss, o);
    }
    if (lane == 0) g_part[row] = make_float4(s, ss, 0.f, 0.f);
}

// ---------------- fused LN + QKV GEMM ----------------------------------------
// R3 loop shape; stats computed inline from g_part; duplicated-A smem +
// direct ull2 B loads remove 6 movs per k per thread.
__global__ void __launch_bounds__(256) qkv_gemm(const float* __restrict__ W,
                                                const float* __restrict__ bias,
                                                const float* __restrict__ gam,
                                                const float* __restrict__ bet) {
    __shared__ float gsh[CH], bsh[CH];
    __shared__ __align__(16) float2 As2[16][64];   // duplicated (a,a)
    __shared__ __align__(16) float  Bs[16][64];

    int tid = threadIdx.x;
    if (tid < 128) { gsh[tid] = gam[tid]; bsh[tid] = bet[tid]; }

    int tx  = tid & 15;
    int ty  = tid >> 4;

    ull acc[4][2];
#pragma unroll
    for (int m = 0; m < 4; m++) { acc[m][0] = 0ull; acc[m][1] = 0ull; }

    int ar = tid >> 2;
    int ac = (tid & 3) << 2;
    int br = tid >> 4;
    int bc = (tid & 15) << 2;

    size_t mBase = (size_t)blockIdx.y * 64;
    const float* Aload = g_h + (mBase + ar) * CH + ac;
    const float* Bload = W + (size_t)br * NQKV + blockIdx.x * 64 + bc;

    // finalize stats inline from partials
    float4 p = g_part[mBase + ar];
    float sum = p.x + p.z;
    float ssum = p.y + p.w;
    float mu  = sum * (1.0f / CH);
    float var = fmaf(-mu, mu, ssum * (1.0f / CH));
    float c1 = rsqrtf(var + EPSLN);     // rstd
    float c0 = -mu * c1;                // -mu*rstd

    __syncthreads();

    for (int k0 = 0; k0 < CH; k0 += 16) {
        float4 av = *(const float4*)(Aload + k0);
        float4 bv = *(const float4*)(Bload + (size_t)k0 * NQKV);
        float l0 = fmaf(fmaf(av.x, c1, c0), gsh[k0 + ac + 0], bsh[k0 + ac + 0]);
        float l1 = fmaf(fmaf(av.y, c1, c0), gsh[k0 + ac + 1], bsh[k0 + ac + 1]);
        float l2 = fmaf(fmaf(av.z, c1, c0), gsh[k0 + ac + 2], bsh[k0 + ac + 2]);
        float l3 = fmaf(fmaf(av.w, c1, c0), gsh[k0 + ac + 3], bsh[k0 + ac + 3]);
        As2[ac + 0][ar] = make_float2(l0, l0);
        As2[ac + 1][ar] = make_float2(l1, l1);
        As2[ac + 2][ar] = make_float2(l2, l2);
        As2[ac + 3][ar] = make_float2(l3, l3);
        *(float4*)&Bs[br][bc] = bv;
        __syncthreads();
#pragma unroll
        for (int k = 0; k < 16; k++) {
            ulonglong2 bq = *(const ulonglong2*)&Bs[k][tx << 2];   // (b0,b1),(b2,b3)
            const ull* Ap = (const ull*)&As2[k][ty << 2];
#pragma unroll
            for (int m = 0; m < 4; m++) {
                ull aa = Ap[m];                                    // (a,a) direct
                acc[m][0] = fma2(aa, bq.x, acc[m][0]);
                acc[m][1] = fma2(aa, bq.y, acc[m][1]);
            }
        }
        __syncthreads();
    }

    int col = blockIdx.x * 64 + (tx << 2);
    float4 bi = *(const float4*)(bias + col);
#pragma unroll
    for (int m = 0; m < 4; m++) {
        size_t row = mBase + (ty << 2) + m;
        float r0, r1, r2, r3;
        upk2(acc[m][0], r0, r1);
        upk2(acc[m][1], r2, r3);
        *(float4*)(g_qkv + row * NQKV + col) =
            make_float4(r0 + bi.x, r1 + bi.y, r2 + bi.z, r3 + bi.w);
    }
}

// ---------------- fused per-channel attention (R3-proven, unchanged) ---------
#define QT 9
#define KT 27
__global__ void __launch_bounds__(128, 8) attn_kernel() {
    int b  = blockIdx.y;
    int q0 = blockIdx.x * QT;
    int c  = threadIdx.x;

    __shared__ float ks[KT][CH];
    __shared__ float vs[KT][CH];

    const float* base = g_qkv + (size_t)b * SEQ * NQKV;
    const float LOG2E = 1.4426950408889634f;

    float qv[QT], num[QT], den[QT];
#pragma unroll
    for (int i = 0; i < QT; i++) {
        qv[i]  = base[(size_t)(q0 + i) * NQKV + c] * LOG2E;
        num[i] = 0.f;
        den[i] = 0.f;
    }

#pragma unroll 1
    for (int kc = 0; kc < SEQ; kc += KT) {
        __syncthreads();
#pragma unroll
        for (int r = 0; r < KT; r++) {
            ks[r][c] = base[(size_t)(kc + r) * NQKV + CH     + c];
            vs[r][c] = base[(size_t)(kc + r) * NQKV + 2 * CH + c];
        }
        __syncthreads();
#pragma unroll 3
        for (int r = 0; r < KT; r++) {
            float kk = ks[r][c];
            float vv = vs[r][c];
#pragma unroll
            for (int i = 0; i < QT; i++) {
                float e = ex2(qv[i] * kk);
                num[i] = fmaf(e, vv, num[i]);
                den[i] += e;
            }
        }
    }

    float* op = g_att + ((size_t)b * SEQ + q0) * CH + c;
#pragma unroll
    for (int i = 0; i < QT; i++) op[(size_t)i * CH] = __fdividef(num[i], den[i]);
}

// ---------------- full GEMM + relu + residual + stats partials ---------------
__global__ void __launch_bounds__(256) full_gemm(const float* __restrict__ B,
                                                 const float* __restrict__ bias) {
    __shared__ __align__(16) float2 As2[16][64];   // duplicated (a,a)
    __shared__ __align__(16) float  Bs[16][64];

    int tid = threadIdx.x;
    int tx  = tid & 15;
    int ty  = tid >> 4;

    ull acc[4][2];
#pragma unroll
    for (int m = 0; m < 4; m++) { acc[m][0] = 0ull; acc[m][1] = 0ull; }

    int ar = tid >> 2;
    int ac = (tid & 3) << 2;
    int br = tid >> 4;
    int bc = (tid & 15) << 2;

    const float* Aload = g_att + ((size_t)blockIdx.y * 64 + ar) * CH + ac;
    const float* Bload = B + (size_t)br * CH + blockIdx.x * 64 + bc;

    for (int k0 = 0; k0 < CH; k0 += 16) {
        float4 av = *(const float4*)(Aload + k0);
        float4 bv = *(const float4*)(Bload + (size_t)k0 * CH);
        As2[ac + 0][ar] = make_float2(av.x, av.x);
        As2[ac + 1][ar] = make_float2(av.y, av.y);
        As2[ac + 2][ar] = make_float2(av.z, av.z);
        As2[ac + 3][ar] = make_float2(av.w, av.w);
        *(float4*)&Bs[br][bc] = bv;
        __syncthreads();
#pragma unroll
        for (int k = 0; k < 16; k++) {
            ulonglong2 bq = *(const ulonglong2*)&Bs[k][tx << 2];
            const ull* Ap = (const ull*)&As2[k][ty << 2];
#pragma unroll
            for (int m = 0; m < 4; m++) {
                ull aa = Ap[m];
                acc[m][0] = fma2(aa, bq.x, acc[m][0]);
                acc[m][1] = fma2(aa, bq.y, acc[m][1]);
            }
        }
        __syncthreads();
    }

    int col = blockIdx.x * 64 + (tx << 2);
    float4 bi = *(const float4*)(bias + col);
    float s[4], ss[4];
#pragma unroll
    for (int m = 0; m < 4; m++) {
        size_t row = (size_t)blockIdx.y * 64 + (ty << 2) + m;
        float r0, r1, r2, r3;
        upk2(acc[m][0], r0, r1);
        upk2(acc[m][1], r2, r3);
        r0 = fmaxf(r0 + bi.x, 0.f);
        r1 = fmaxf(r1 + bi.y, 0.f);
        r2 = fmaxf(r2 + bi.z, 0.f);
        r3 = fmaxf(r3 + bi.w, 0.f);
        float* hrow = g_h + row * CH + col;
        float4 old = *(const float4*)hrow;
        float h0 = old.x + r0, h1 = old.y + r1, h2 = old.z + r2, h3 = old.w + r3;
        *(float4*)hrow = make_float4(h0, h1, h2, h3);
        s[m]  = h0 + h1 + h2 + h3;
        ss[m] = fmaf(h0, h0, fmaf(h1, h1, fmaf(h2, h2, h3 * h3)));
    }
#pragma unroll
    for (int m = 0; m < 4; m++) {
#pragma unroll
        for (int o = 8; o; o >>= 1) {
            s[m]  += __shfl_xor_sync(0xffffffffu, s[m], o);
            ss[m] += __shfl_xor_sync(0xffffffffu, ss[m], o);
        }
    }
    if (tx == 0) {
#pragma unroll
        for (int m = 0; m < 4; m++) {
            size_t row = (size_t)blockIdx.y * 64 + (ty << 2) + m;
            float2* dst = (float2*)&g_part[row];        // two float2 halves
            dst[blockIdx.x] = make_float2(s[m], ss[m]); // block 0 -> .xy, 1 -> .zw
        }
    }
}

// ---------------- final projection: out = h @ out_w + out_b ------------------
__global__ void __launch_bounds__(256) outproj_kernel(const float* __restrict__ ow,
                                                      const float* __restrict__ ob,
                                                      float* __restrict__ out) {
    int row  = blockIdx.x * 8 + (threadIdx.x >> 5);
    int lane = threadIdx.x & 31;
    const float* hr = g_h + (size_t)row * CH;
    float a0 = 0.f, a1 = 0.f, a2 = 0.f, a3 = 0.f;
#pragma unroll
    for (int j = 0; j < 4; j++) {
        int cidx = lane + 32 * j;
        float hv = hr[cidx];
        const float* w = ow + cidx * 4;
        a0 = fmaf(hv, w[0], a0);
        a1 = fmaf(hv, w[1], a1);
        a2 = fmaf(hv, w[2], a2);
        a3 = fmaf(hv, w[3], a3);
    }
#pragma unroll
    for (int o = 16; o; o >>= 1) {
        a0 += __shfl_xor_sync(0xffffffffu, a0, o);
        a1 += __shfl_xor_sync(0xffffffffu, a1, o);
        a2 += __shfl_xor_sync(0xffffffffu, a2, o);
        a3 += __shfl_xor_sync(0xffffffffu, a3, o);
    }
    if (lane == 0) {
        *(float4*)(out + (size_t)row * 4) =
            make_float4(a0 + ob[0], a1 + ob[1], a2 + ob[2], a3 + ob[3]);
    }
}

// ---------------- launch -----------------------------------------------------
extern "C" void kernel_launch(void* const* d_in, const int* in_sizes, int n_in,
                              void* d_out, int out_size) {
    const float* x      = (const float*)d_in[0];
    const float* in_w   = (const float*)d_in[1];
    const float* in_b   = (const float*)d_in[2];
    const float* ln_g   = (const float*)d_in[3];
    const float* ln_b   = (const float*)d_in[4];
    const float* qkv_w  = (const float*)d_in[5];
    const float* qkv_b  = (const float*)d_in[6];
    const float* full_w = (const float*)d_in[7];
    const float* full_b = (const float*)d_in[8];
    const float* out_w  = (const float*)d_in[9];
    const float* out_b  = (const float*)d_in[10];
    float* out = (float*)d_out;

    inproj_kernel<<<MROWS / 8, 256>>>(x, in_w, in_b);

    for (int l = 0; l < 4; l++) {
        qkv_gemm<<<dim3(NQKV / 64, MROWS / 64), 256>>>(
            qkv_w + (size_t)l * CH * NQKV, qkv_b + l * NQKV,
            ln_g + l * CH, ln_b + l * CH);
        attn_kernel<<<dim3(SEQ / QT, TBS), 128>>>();
        full_gemm<<<dim3(CH / 64, MROWS / 64), 256>>>(
            full_w + (size_t)l * CH * CH, full_b + l * CH);
    }

    outproj_kernel<<<MROWS / 8, 256>>>(out_w, out_b, out);
}

// round 13
// speedup vs baseline: 1.2195x; 1.2195x over previous
#include <cuda_runtime.h>

// ---------------- problem constants ----------------
#define TBS   128          // T*B = 4*32
#define SEQ   81           // 9*9
#define CH    128          // width C
#define MROWS (TBS*SEQ)    // 10368 rows
#define NQKV  384          // 3*C
#define EPSLN 1e-5f

typedef unsigned long long ull;

// ---------------- scratch (static device globals; no allocation) ------------
__device__ float  g_h  [MROWS*CH];    // residual stream
__device__ float2 g_stats[MROWS];     // per-row (mu, rstd) of g_h
__device__ float  g_qkv[MROWS*NQKV];  // qkv projection

// ---------------- packed f32x2 helpers --------------------------------------
__device__ __forceinline__ ull pk2(float x, float y) {
    ull r;
    asm("mov.b64 %0, {%1, %2};"
        : "=l"(r) : "r"(__float_as_uint(x)), "r"(__float_as_uint(y)));
    return r;
}
__device__ __forceinline__ ull fma2(ull a, ull b, ull c) {
    ull d;
    asm("fma.rn.f32x2 %0, %1, %2, %3;" : "=l"(d) : "l"(a), "l"(b), "l"(c));
    return d;
}
__device__ __forceinline__ void upk2(ull v, float& x, float& y) {
    unsigned int lo, hi;
    asm("mov.b64 {%0, %1}, %2;" : "=r"(lo), "=r"(hi) : "l"(v));
    x = __uint_as_float(lo);
    y = __uint_as_float(hi);
}
__device__ __forceinline__ float ex2(float x) {
    float r;
    asm("ex2.approx.f32 %0, %1;" : "=f"(r) : "f"(x));
    return r;
}

// ---------------- input projection + LN stats --------------------------------
__global__ void __launch_bounds__(256) inproj_kernel(const float* __restrict__ x,
                                                     const float* __restrict__ in_w,
                                                     const float* __restrict__ in_b) {
    int row  = blockIdx.x * 8 + (threadIdx.x >> 5);
    int lane = threadIdx.x & 31;
    float x0 = __ldg(&x[row * 2]);
    float x1 = __ldg(&x[row * 2 + 1]);
    float s = 0.f, ss = 0.f;
    float* hr = g_h + (size_t)row * CH;
#pragma unroll
    for (int j = 0; j < 4; j++) {
        int c = lane + 32 * j;
        float h = fmaf(x0, in_w[c], fmaf(x1, in_w[CH + c], in_b[c]));
        hr[c] = h;
        s += h;
        ss = fmaf(h, h, ss);
    }
#pragma unroll
    for (int o = 16; o; o >>= 1) {
        s  += __shfl_xor_sync(0xffffffffu, s, o);
        ss += __shfl_xor_sync(0xffffffffu, ss, o);
    }
    if (lane == 0) {
        float mu  = s * (1.0f / CH);
        float var = fmaf(-mu, mu, ss * (1.0f / CH));
        g_stats[row] = make_float2(mu, rsqrtf(var + EPSLN));
    }
}

// ---------------- fused LN + QKV GEMM (R10/R11 measured form) ----------------
__global__ void __launch_bounds__(256) qkv_gemm(const float* __restrict__ W,
                                                const float* __restrict__ bias,
                                                const float* __restrict__ gam,
                                                const float* __restrict__ bet) {
    __shared__ float gsh[CH], bsh[CH];
    __shared__ float As[16][64];
    __shared__ float Bs[16][64];

    int tid = threadIdx.x;
    if (tid < 128) { gsh[tid] = gam[tid]; bsh[tid] = bet[tid]; }

    int tx  = tid & 15;
    int ty  = tid >> 4;

    ull acc[4][2];
#pragma unroll
    for (int m = 0; m < 4; m++) { acc[m][0] = 0ull; acc[m][1] = 0ull; }

    int ar = tid >> 2;
    int ac = (tid & 3) << 2;
    int br = tid >> 4;
    int bc = (tid & 15) << 2;

    size_t mBase = (size_t)blockIdx.y * 64;
    const float* Aload = g_h + (mBase + ar) * CH + ac;
    const float* Bload = W + (size_t)br * NQKV + blockIdx.x * 64 + bc;
    float2 st = g_stats[mBase + ar];
    float c1 = st.y;               // rstd
    float c0 = -st.x * st.y;       // -mu*rstd

    __syncthreads();

    for (int k0 = 0; k0 < CH; k0 += 16) {
        float4 av = *(const float4*)(Aload + k0);
        float4 bv = *(const float4*)(Bload + (size_t)k0 * NQKV);
        As[ac + 0][ar] = fmaf(fmaf(av.x, c1, c0), gsh[k0 + ac + 0], bsh[k0 + ac + 0]);
        As[ac + 1][ar] = fmaf(fmaf(av.y, c1, c0), gsh[k0 + ac + 1], bsh[k0 + ac + 1]);
        As[ac + 2][ar] = fmaf(fmaf(av.z, c1, c0), gsh[k0 + ac + 2], bsh[k0 + ac + 2]);
        As[ac + 3][ar] = fmaf(fmaf(av.w, c1, c0), gsh[k0 + ac + 3], bsh[k0 + ac + 3]);
        *(float4*)&Bs[br][bc] = bv;
        __syncthreads();
#pragma unroll
        for (int k = 0; k < 16; k++) {
            float4 b4 = *(const float4*)&Bs[k][tx << 2];
            ull b01 = pk2(b4.x, b4.y);
            ull b23 = pk2(b4.z, b4.w);
#pragma unroll
            for (int m = 0; m < 4; m++) {
                float a = As[k][(ty << 2) + m];
                ull aa = pk2(a, a);
                acc[m][0] = fma2(aa, b01, acc[m][0]);
                acc[m][1] = fma2(aa, b23, acc[m][1]);
            }
        }
        __syncthreads();
    }

    int col = blockIdx.x * 64 + (tx << 2);
    float4 bi = *(const float4*)(bias + col);
#pragma unroll
    for (int m = 0; m < 4; m++) {
        size_t row = mBase + (ty << 2) + m;
        float r0, r1, r2, r3;
        upk2(acc[m][0], r0, r1);
        upk2(acc[m][1], r2, r3);
        *(float4*)(g_qkv + row * NQKV + col) =
            make_float4(r0 + bi.x, r1 + bi.y, r2 + bi.z, r3 + bi.w);
    }
}

// ---------------- fused attention + FFN + residual + LN stats ----------------
// Attention part is R3-proven. Then: att -> smem (reusing ks), FFN through the
// idle FMA pipe, bias+relu+residual into g_h, in-block LN stats (rows complete).
#define QT 9
#define KT 27
__global__ void __launch_bounds__(128, 8) attn_ffn_kernel(const float* __restrict__ W,
                                                          const float* __restrict__ bias) {
    int b  = blockIdx.y;
    int q0 = blockIdx.x * QT;
    int c  = threadIdx.x;

    __shared__ float ks[KT][CH];
    __shared__ float vs[KT][CH];

    const float* base = g_qkv + (size_t)b * SEQ * NQKV;
    const float LOG2E = 1.4426950408889634f;

    float qv[QT], num[QT], den[QT];
#pragma unroll
    for (int i = 0; i < QT; i++) {
        qv[i]  = base[(size_t)(q0 + i) * NQKV + c] * LOG2E;
        num[i] = 0.f;
        den[i] = 0.f;
    }

#pragma unroll 1
    for (int kc = 0; kc < SEQ; kc += KT) {
        __syncthreads();
#pragma unroll
        for (int r = 0; r < KT; r++) {
            ks[r][c] = base[(size_t)(kc + r) * NQKV + CH     + c];
            vs[r][c] = base[(size_t)(kc + r) * NQKV + 2 * CH + c];
        }
        __syncthreads();
#pragma unroll 3
        for (int r = 0; r < KT; r++) {
            float kk = ks[r][c];
            float vv = vs[r][c];
#pragma unroll
            for (int i = 0; i < QT; i++) {
                float e = ex2(qv[i] * kk);
                num[i] = fmaf(e, vv, num[i]);
                den[i] += e;
            }
        }
    }

    // ---- stage att rows in smem (reuse ks; all warps done reading it) ------
    __syncthreads();
    float (*att_s)[CH] = ks;
#pragma unroll
    for (int i = 0; i < QT; i++) att_s[i][c] = __fdividef(num[i], den[i]);
    __syncthreads();

    // ---- FFN: y[i] = sum_k att[i][k] * W[k][c]  (FMA pipe, idle until now) --
    float y[QT];
#pragma unroll
    for (int i = 0; i < QT; i++) y[i] = 0.f;
#pragma unroll 2
    for (int k = 0; k < CH; k += 4) {
        float w0 = W[(size_t)(k + 0) * CH + c];
        float w1 = W[(size_t)(k + 1) * CH + c];
        float w2 = W[(size_t)(k + 2) * CH + c];
        float w3 = W[(size_t)(k + 3) * CH + c];
#pragma unroll
        for (int i = 0; i < QT; i++) {
            float4 a = *(const float4*)&att_s[i][k];   // LDS.128 broadcast
            y[i] = fmaf(a.x, w0, y[i]);
            y[i] = fmaf(a.y, w1, y[i]);
            y[i] = fmaf(a.z, w2, y[i]);
            y[i] = fmaf(a.w, w3, y[i]);
        }
    }

    // ---- bias + relu + residual + write h; collect per-row stats -----------
    float bb = bias[c];
    size_t rowBase = (size_t)b * SEQ + q0;
    int wid  = c >> 5;
    int lane = c & 31;
    float* rs  = (float*)vs;           // [4][QT] partial sums (vs is dead)
    float* rss = rs + 4 * QT;          // [4][QT] partial sumsq

    float hn[QT];
#pragma unroll
    for (int i = 0; i < QT; i++) {
        float v = fmaxf(y[i] + bb, 0.f);
        float* hp = g_h + (rowBase + i) * CH + c;
        float h = *hp + v;
        *hp = h;
        hn[i] = h;
    }
#pragma unroll
    for (int i = 0; i < QT; i++) {
        float s  = hn[i];
        float ss = hn[i] * hn[i];
#pragma unroll
        for (int o = 16; o; o >>= 1) {
            s  += __shfl_xor_sync(0xffffffffu, s, o);
            ss += __shfl_xor_sync(0xffffffffu, ss, o);
        }
        if (lane == 0) { rs[wid * QT + i] = s; rss[wid * QT + i] = ss; }
    }
    __syncthreads();
    if (c < QT) {
        float s  = rs[c]  + rs[QT + c]  + rs[2 * QT + c]  + rs[3 * QT + c];
        float ss = rss[c] + rss[QT + c] + rss[2 * QT + c] + rss[3 * QT + c];
        float mu  = s * (1.0f / CH);
        float var = fmaf(-mu, mu, ss * (1.0f / CH));
        g_stats[rowBase + c] = make_float2(mu, rsqrtf(var + EPSLN));
    }
}

// ---------------- final projection: out = h @ out_w + out_b ------------------
__global__ void __launch_bounds__(256) outproj_kernel(const float* __restrict__ ow,
                                                      const float* __restrict__ ob,
                                                      float* __restrict__ out) {
    int row  = blockIdx.x * 8 + (threadIdx.x >> 5);
    int lane = threadIdx.x & 31;
    const float* hr = g_h + (size_t)row * CH;
    float a0 = 0.f, a1 = 0.f, a2 = 0.f, a3 = 0.f;
#pragma unroll
    for (int j = 0; j < 4; j++) {
        int cidx = lane + 32 * j;
        float hv = hr[cidx];
        const float* w = ow + cidx * 4;
        a0 = fmaf(hv, w[0], a0);
        a1 = fmaf(hv, w[1], a1);
        a2 = fmaf(hv, w[2], a2);
        a3 = fmaf(hv, w[3], a3);
    }
#pragma unroll
    for (int o = 16; o; o >>= 1) {
        a0 += __shfl_xor_sync(0xffffffffu, a0, o);
        a1 += __shfl_xor_sync(0xffffffffu, a1, o);
        a2 += __shfl_xor_sync(0xffffffffu, a2, o);
        a3 += __shfl_xor_sync(0xffffffffu, a3, o);
    }
    if (lane == 0) {
        *(float4*)(out + (size_t)row * 4) =
            make_float4(a0 + ob[0], a1 + ob[1], a2 + ob[2], a3 + ob[3]);
    }
}

// ---------------- launch -----------------------------------------------------
extern "C" void kernel_launch(void* const* d_in, const int* in_sizes, int n_in,
                              void* d_out, int out_size) {
    const float* x      = (const float*)d_in[0];
    const float* in_w   = (const float*)d_in[1];
    const float* in_b   = (const float*)d_in[2];
    const float* ln_g   = (const float*)d_in[3];
    const float* ln_b   = (const float*)d_in[4];
    const float* qkv_w  = (const float*)d_in[5];
    const float* qkv_b  = (const float*)d_in[6];
    const float* full_w = (const float*)d_in[7];
    const float* full_b = (const float*)d_in[8];
    const float* out_w  = (const float*)d_in[9];
    const float* out_b  = (const float*)d_in[10];
    float* out = (float*)d_out;

    inproj_kernel<<<MROWS / 8, 256>>>(x, in_w, in_b);

    for (int l = 0; l < 4; l++) {
        qkv_gemm<<<dim3(NQKV / 64, MROWS / 64), 256>>>(
            qkv_w + (size_t)l * CH * NQKV, qkv_b + l * NQKV,
            ln_g + l * CH, ln_b + l * CH);
        attn_ffn_kernel<<<dim3(SEQ / QT, TBS), 128>>>(
            full_w + (size_t)l * CH * CH, full_b + l * CH);
    }

    outproj_kernel<<<MROWS / 8, 256>>>(out_w, out_b, out);
}

// round 14
// speedup vs baseline: 1.2283x; 1.0072x over previous
#include <cuda_runtime.h>

// ---------------- problem constants ----------------
#define TBS   128          // T*B = 4*32
#define SEQ   81           // 9*9
#define CH    128          // width C
#define MROWS (TBS*SEQ)    // 10368 rows
#define NQKV  384          // 3*C
#define EPSLN 1e-5f

typedef unsigned long long ull;

// ---------------- scratch (static device globals; no allocation) ------------
__device__ float  g_h  [MROWS*CH];    // residual stream
__device__ float2 g_stats[MROWS];     // per-row (mu, rstd) of g_h
__device__ float  g_qkv[MROWS*NQKV];  // qkv projection

// ---------------- packed f32x2 helpers --------------------------------------
__device__ __forceinline__ ull pk2(float x, float y) {
    ull r;
    asm("mov.b64 %0, {%1, %2};"
        : "=l"(r) : "r"(__float_as_uint(x)), "r"(__float_as_uint(y)));
    return r;
}
__device__ __forceinline__ ull fma2(ull a, ull b, ull c) {
    ull d;
    asm("fma.rn.f32x2 %0, %1, %2, %3;" : "=l"(d) : "l"(a), "l"(b), "l"(c));
    return d;
}
__device__ __forceinline__ void upk2(ull v, float& x, float& y) {
    unsigned int lo, hi;
    asm("mov.b64 {%0, %1}, %2;" : "=r"(lo), "=r"(hi) : "l"(v));
    x = __uint_as_float(lo);
    y = __uint_as_float(hi);
}
__device__ __forceinline__ float ex2(float x) {
    float r;
    asm("ex2.approx.f32 %0, %1;" : "=f"(r) : "f"(x));
    return r;
}

// ---------------- input projection + LN stats --------------------------------
__global__ void __launch_bounds__(256) inproj_kernel(const float* __restrict__ x,
                                                     const float* __restrict__ in_w,
                                                     const float* __restrict__ in_b) {
    int row  = blockIdx.x * 8 + (threadIdx.x >> 5);
    int lane = threadIdx.x & 31;
    float x0 = __ldg(&x[row * 2]);
    float x1 = __ldg(&x[row * 2 + 1]);
    float s = 0.f, ss = 0.f;
    float* hr = g_h + (size_t)row * CH;
#pragma unroll
    for (int j = 0; j < 4; j++) {
        int c = lane + 32 * j;
        float h = fmaf(x0, in_w[c], fmaf(x1, in_w[CH + c], in_b[c]));
        hr[c] = h;
        s += h;
        ss = fmaf(h, h, ss);
    }
#pragma unroll
    for (int o = 16; o; o >>= 1) {
        s  += __shfl_xor_sync(0xffffffffu, s, o);
        ss += __shfl_xor_sync(0xffffffffu, ss, o);
    }
    if (lane == 0) {
        float mu  = s * (1.0f / CH);
        float var = fmaf(-mu, mu, ss * (1.0f / CH));
        g_stats[row] = make_float2(mu, rsqrtf(var + EPSLN));
    }
}

// ---------------- fused LN + QKV GEMM (vectorized A fragment read) -----------
__global__ void __launch_bounds__(256) qkv_gemm(const float* __restrict__ W,
                                                const float* __restrict__ bias,
                                                const float* __restrict__ gam,
                                                const float* __restrict__ bet) {
    __shared__ float gsh[CH], bsh[CH];
    __shared__ __align__(16) float As[16][64];
    __shared__ __align__(16) float Bs[16][64];

    int tid = threadIdx.x;
    if (tid < 128) { gsh[tid] = gam[tid]; bsh[tid] = bet[tid]; }

    int tx  = tid & 15;
    int ty  = tid >> 4;

    ull acc[4][2];
#pragma unroll
    for (int m = 0; m < 4; m++) { acc[m][0] = 0ull; acc[m][1] = 0ull; }

    int ar = tid >> 2;
    int ac = (tid & 3) << 2;
    int br = tid >> 4;
    int bc = (tid & 15) << 2;

    size_t mBase = (size_t)blockIdx.y * 64;
    const float* Aload = g_h + (mBase + ar) * CH + ac;
    const float* Bload = W + (size_t)br * NQKV + blockIdx.x * 64 + bc;
    float2 st = g_stats[mBase + ar];
    float c1 = st.y;               // rstd
    float c0 = -st.x * st.y;       // -mu*rstd

    __syncthreads();

    for (int k0 = 0; k0 < CH; k0 += 16) {
        float4 av = *(const float4*)(Aload + k0);
        float4 bv = *(const float4*)(Bload + (size_t)k0 * NQKV);
        As[ac + 0][ar] = fmaf(fmaf(av.x, c1, c0), gsh[k0 + ac + 0], bsh[k0 + ac + 0]);
        As[ac + 1][ar] = fmaf(fmaf(av.y, c1, c0), gsh[k0 + ac + 1], bsh[k0 + ac + 1]);
        As[ac + 2][ar] = fmaf(fmaf(av.z, c1, c0), gsh[k0 + ac + 2], bsh[k0 + ac + 2]);
        As[ac + 3][ar] = fmaf(fmaf(av.w, c1, c0), gsh[k0 + ac + 3], bsh[k0 + ac + 3]);
        *(float4*)&Bs[br][bc] = bv;
        __syncthreads();
        // NOTE: As rows are NOT float4-aligned per row start? As[k] is 64 floats,
        // row base = k*256B, 16B aligned; &As[k][4*ty] is 16B aligned. OK.
#pragma unroll
        for (int k = 0; k < 16; k++) {
            float4 a4 = *(const float4*)&As[k][ty << 2];   // 1 LDS.128, broadcast
            float4 b4 = *(const float4*)&Bs[k][tx << 2];   // 1 LDS.128, 2 wf
            ull b01 = pk2(b4.x, b4.y);
            ull b23 = pk2(b4.z, b4.w);
            ull a0 = pk2(a4.x, a4.x);
            ull a1 = pk2(a4.y, a4.y);
            ull a2 = pk2(a4.z, a4.z);
            ull a3 = pk2(a4.w, a4.w);
            acc[0][0] = fma2(a0, b01, acc[0][0]);
            acc[0][1] = fma2(a0, b23, acc[0][1]);
            acc[1][0] = fma2(a1, b01, acc[1][0]);
            acc[1][1] = fma2(a1, b23, acc[1][1]);
            acc[2][0] = fma2(a2, b01, acc[2][0]);
            acc[2][1] = fma2(a2, b23, acc[2][1]);
            acc[3][0] = fma2(a3, b01, acc[3][0]);
            acc[3][1] = fma2(a3, b23, acc[3][1]);
        }
        __syncthreads();
    }

    int col = blockIdx.x * 64 + (tx << 2);
    float4 bi = *(const float4*)(bias + col);
#pragma unroll
    for (int m = 0; m < 4; m++) {
        size_t row = mBase + (ty << 2) + m;
        float r0, r1, r2, r3;
        upk2(acc[m][0], r0, r1);
        upk2(acc[m][1], r2, r3);
        *(float4*)(g_qkv + row * NQKV + col) =
            make_float4(r0 + bi.x, r1 + bi.y, r2 + bi.z, r3 + bi.w);
    }
}

// ---------------- fused attention + FFN + residual + LN stats (R13 WIN) ------
#define QT 9
#define KT 27
__global__ void __launch_bounds__(128, 8) attn_ffn_kernel(const float* __restrict__ W,
                                                          const float* __restrict__ bias) {
    int b  = blockIdx.y;
    int q0 = blockIdx.x * QT;
    int c  = threadIdx.x;

    __shared__ float ks[KT][CH];
    __shared__ float vs[KT][CH];

    const float* base = g_qkv + (size_t)b * SEQ * NQKV;
    const float LOG2E = 1.4426950408889634f;

    float qv[QT], num[QT], den[QT];
#pragma unroll
    for (int i = 0; i < QT; i++) {
        qv[i]  = base[(size_t)(q0 + i) * NQKV + c] * LOG2E;
        num[i] = 0.f;
        den[i] = 0.f;
    }

#pragma unroll 1
    for (int kc = 0; kc < SEQ; kc += KT) {
        __syncthreads();
#pragma unroll
        for (int r = 0; r < KT; r++) {
            ks[r][c] = base[(size_t)(kc + r) * NQKV + CH     + c];
            vs[r][c] = base[(size_t)(kc + r) * NQKV + 2 * CH + c];
        }
        __syncthreads();
#pragma unroll 3
        for (int r = 0; r < KT; r++) {
            float kk = ks[r][c];
            float vv = vs[r][c];
#pragma unroll
            for (int i = 0; i < QT; i++) {
                float e = ex2(qv[i] * kk);
                num[i] = fmaf(e, vv, num[i]);
                den[i] += e;
            }
        }
    }

    // ---- stage att rows in smem (reuse ks; all warps done reading it) ------
    __syncthreads();
    float (*att_s)[CH] = ks;
#pragma unroll
    for (int i = 0; i < QT; i++) att_s[i][c] = __fdividef(num[i], den[i]);
    __syncthreads();

    // ---- FFN: y[i] = sum_k att[i][k] * W[k][c]  (idle FMA pipe) ------------
    float y[QT];
#pragma unroll
    for (int i = 0; i < QT; i++) y[i] = 0.f;
#pragma unroll 2
    for (int k = 0; k < CH; k += 4) {
        float w0 = W[(size_t)(k + 0) * CH + c];
        float w1 = W[(size_t)(k + 1) * CH + c];
        float w2 = W[(size_t)(k + 2) * CH + c];
        float w3 = W[(size_t)(k + 3) * CH + c];
#pragma unroll
        for (int i = 0; i < QT; i++) {
            float4 a = *(const float4*)&att_s[i][k];   // LDS.128 broadcast
            y[i] = fmaf(a.x, w0, y[i]);
            y[i] = fmaf(a.y, w1, y[i]);
            y[i] = fmaf(a.z, w2, y[i]);
            y[i] = fmaf(a.w, w3, y[i]);
        }
    }

    // ---- bias + relu + residual + write h; collect per-row stats -----------
    float bb = bias[c];
    size_t rowBase = (size_t)b * SEQ + q0;
    int wid  = c >> 5;
    int lane = c & 31;
    float* rs  = (float*)vs;           // [4][QT] partial sums (vs is dead)
    float* rss = rs + 4 * QT;          // [4][QT] partial sumsq

    float hn[QT];
#pragma unroll
    for (int i = 0; i < QT; i++) {
        float v = fmaxf(y[i] + bb, 0.f);
        float* hp = g_h + (rowBase + i) * CH + c;
        float h = *hp + v;
        *hp = h;
        hn[i] = h;
    }
#pragma unroll
    for (int i = 0; i < QT; i++) {
        float s  = hn[i];
        float ss = hn[i] * hn[i];
#pragma unroll
        for (int o = 16; o; o >>= 1) {
            s  += __shfl_xor_sync(0xffffffffu, s, o);
            ss += __shfl_xor_sync(0xffffffffu, ss, o);
        }
        if (lane == 0) { rs[wid * QT + i] = s; rss[wid * QT + i] = ss; }
    }
    __syncthreads();
    if (c < QT) {
        float s  = rs[c]  + rs[QT + c]  + rs[2 * QT + c]  + rs[3 * QT + c];
        float ss = rss[c] + rss[QT + c] + rss[2 * QT + c] + rss[3 * QT + c];
        float mu  = s * (1.0f / CH);
        float var = fmaf(-mu, mu, ss * (1.0f / CH));
        g_stats[rowBase + c] = make_float2(mu, rsqrtf(var + EPSLN));
    }
}

// ---------------- final projection: out = h @ out_w + out_b ------------------
__global__ void __launch_bounds__(256) outproj_kernel(const float* __restrict__ ow,
                                                      const float* __restrict__ ob,
                                                      float* __restrict__ out) {
    int row  = blockIdx.x * 8 + (threadIdx.x >> 5);
    int lane = threadIdx.x & 31;
    const float* hr = g_h + (size_t)row * CH;
    float a0 = 0.f, a1 = 0.f, a2 = 0.f, a3 = 0.f;
#pragma unroll
    for (int j = 0; j < 4; j++) {
        int cidx = lane + 32 * j;
        float hv = hr[cidx];
        const float* w = ow + cidx * 4;
        a0 = fmaf(hv, w[0], a0);
        a1 = fmaf(hv, w[1], a1);
        a2 = fmaf(hv, w[2], a2);
        a3 = fmaf(hv, w[3], a3);
    }
#pragma unroll
    for (int o = 16; o; o >>= 1) {
        a0 += __shfl_xor_sync(0xffffffffu, a0, o);
        a1 += __shfl_xor_sync(0xffffffffu, a1, o);
        a2 += __shfl_xor_sync(0xffffffffu, a2, o);
        a3 += __shfl_xor_sync(0xffffffffu, a3, o);
    }
    if (lane == 0) {
        *(float4*)(out + (size_t)row * 4) =
            make_float4(a0 + ob[0], a1 + ob[1], a2 + ob[2], a3 + ob[3]);
    }
}

// ---------------- launch -----------------------------------------------------
extern "C" void kernel_launch(void* const* d_in, const int* in_sizes, int n_in,
                              void* d_out, int out_size) {
    const float* x      = (const float*)d_in[0];
    const float* in_w   = (const float*)d_in[1];
    const float* in_b   = (const float*)d_in[2];
    const float* ln_g   = (const float*)d_in[3];
    const float* ln_b   = (const float*)d_in[4];
    const float* qkv_w  = (const float*)d_in[5];
    const float* qkv_b  = (const float*)d_in[6];
    const float* full_w = (const float*)d_in[7];
    const float* full_b = (const float*)d_in[8];
    const float* out_w  = (const float*)d_in[9];
    const float* out_b  = (const float*)d_in[10];
    float* out = (float*)d_out;

    inproj_kernel<<<MROWS / 8, 256>>>(x, in_w, in_b);

    for (int l = 0; l < 4; l++) {
        qkv_gemm<<<dim3(NQKV / 64, MROWS / 64), 256>>>(
            qkv_w + (size_t)l * CH * NQKV, qkv_b + l * NQKV,
            ln_g + l * CH, ln_b + l * CH);
        attn_ffn_kernel<<<dim3(SEQ / QT, TBS), 128>>>(
            full_w + (size_t)l * CH * CH, full_b + l * CH);
    }

    outproj_kernel<<<MROWS / 8, 256>>>(out_w, out_b, out);
}